// round 9
// baseline (speedup 1.0000x reference)
#include <cuda_runtime.h>
#include <math.h>
#include <stdint.h>

#define TLEN   1024
#define BATCH  4
#define EMBED  1024
#define NH     16
#define HD     64
#define QSCALE 0.125f
#define MROWS  (TLEN * BATCH)   // 4096

// Scratch (static device globals — no cudaMalloc anywhere)
__device__ float g_Q[BATCH * NH * TLEN * HD];                 // [b,h,t,d], pre-scaled
__device__ float g_K[BATCH * NH * TLEN * HD];
__device__ float g_V[BATCH * NH * TLEN * HD];
__device__ float g_P[(size_t)BATCH * NH * TLEN * TLEN];       // unnormalized exp tiles
__device__ float g_C[BATCH * NH * TLEN * 16];                 // per-(row,tile) corrections
__device__ float g_A[MROWS * EMBED];                          // attention context [t,b,e]

__device__ __forceinline__ uint32_t f2tf(float f) {
    uint32_t u;
    asm("cvt.rna.tf32.f32 %0, %1;" : "=r"(u) : "f"(f));
    return u;
}

// Column permutation within each 8-group: (c, c+4) -> (2c, 2c+1), so MMA
// fragment column pairs become adjacent and load with a single LDS.64.
__device__ __forceinline__ int perm8c(int c) {
    return (c & ~7) | (((c & 3) << 1) | ((c >> 2) & 1));
}

__device__ __forceinline__ void mma_tf32(float* d, const uint32_t* a, const uint32_t* b) {
    asm volatile(
        "mma.sync.aligned.m16n8k8.row.col.f32.tf32.tf32.f32 "
        "{%0,%1,%2,%3}, {%4,%5,%6,%7}, {%8,%9}, {%0,%1,%2,%3};"
        : "+f"(d[0]), "+f"(d[1]), "+f"(d[2]), "+f"(d[3])
        : "r"(a[0]), "r"(a[1]), "r"(a[2]), "r"(a[3]), "r"(b[0]), "r"(b[1]));
}

// ---------------------------------------------------------------------------
// TF32 tensor-core GEMM: C[M,N] = A[M,K] @ B[N,K]^T + bias
// Double-buffered; paired-column smem layout; LDS.64 fragment loads.
// ---------------------------------------------------------------------------
#define GEMM_SMEM_WORDS (4 * 128 * 36)
#define AS(buf, r, c) As[(buf) * 4608 + (r) * 36 + (c)]
#define BS(buf, r, c) Bs[(buf) * 4608 + (r) * 36 + (c)]

template <int EPI>
__global__ __launch_bounds__(256) void k_gemm_tf32(const float* __restrict__ Ain,
                                                   const float* __restrict__ B,
                                                   const float* __restrict__ bias,
                                                   float* __restrict__ C,
                                                   int K) {
    const float* A = (EPI == 0) ? Ain : (const float*)g_A;
    extern __shared__ uint32_t smraw[];
    uint32_t* As = smraw;
    uint32_t* Bs = smraw + 2 * 4608;
    const int tid  = threadIdx.x;
    const int lane = tid & 31;
    const int wid  = tid >> 5;
    const int wm   = (wid & 1) << 6;
    const int wn   = (wid >> 1) << 5;
    const int m0   = blockIdx.y << 7;
    const int n0   = blockIdx.x << 7;
    const int ldr = tid >> 3;
    const int ldc = (tid & 7) << 2;
    const int stc = (ldc & 24) | ((ldc >> 2) & 1);   // permuted store base, +0/2/4/6
    const int g4 = lane >> 2;
    const int g1 = lane & 3;

    float acc[4][4][4] = {};
    float4 av[4], bv[4];

    const float* Abase = A + (size_t)(m0 + ldr) * K + ldc;
    const float* Bbase = B + (size_t)(n0 + ldr) * K + ldc;

    #pragma unroll
    for (int r = 0; r < 4; r++) {
        av[r] = *(const float4*)(Abase + (size_t)(r << 5) * K);
        bv[r] = *(const float4*)(Bbase + (size_t)(r << 5) * K);
    }
    #pragma unroll
    for (int r = 0; r < 4; r++) {
        uint32_t* pa = &AS(0, (r << 5) + ldr, stc);
        uint32_t* pb = &BS(0, (r << 5) + ldr, stc);
        pa[0] = f2tf(av[r].x); pa[2] = f2tf(av[r].y); pa[4] = f2tf(av[r].z); pa[6] = f2tf(av[r].w);
        pb[0] = f2tf(bv[r].x); pb[2] = f2tf(bv[r].y); pb[4] = f2tf(bv[r].z); pb[6] = f2tf(bv[r].w);
    }
    __syncthreads();

    int cur = 0;
    for (int k0 = 0; k0 < K; k0 += 32) {
        const bool has_next = (k0 + 32 < K);
        if (has_next) {
            #pragma unroll
            for (int r = 0; r < 4; r++) {
                av[r] = *(const float4*)(Abase + (size_t)(r << 5) * K + k0 + 32);
                bv[r] = *(const float4*)(Bbase + (size_t)(r << 5) * K + k0 + 32);
            }
        }
        #pragma unroll
        for (int kk = 0; kk < 32; kk += 8) {
            const int pc = kk + (g1 << 1);
            uint32_t a[4][4], b[4][2];
            #pragma unroll
            for (int im = 0; im < 4; im++) {
                int mr = wm + (im << 4) + g4;
                uint2 lo = *(const uint2*)&AS(cur, mr    , pc);
                uint2 hi = *(const uint2*)&AS(cur, mr + 8, pc);
                a[im][0] = lo.x; a[im][1] = hi.x; a[im][2] = lo.y; a[im][3] = hi.y;
            }
            #pragma unroll
            for (int jn = 0; jn < 4; jn++) {
                int nr = wn + (jn << 3) + g4;
                uint2 bb = *(const uint2*)&BS(cur, nr, pc);
                b[jn][0] = bb.x; b[jn][1] = bb.y;
            }
            #pragma unroll
            for (int im = 0; im < 4; im++)
                #pragma unroll
                for (int jn = 0; jn < 4; jn++)
                    mma_tf32(acc[im][jn], a[im], b[jn]);
        }
        if (has_next) {
            int nxt = cur ^ 1;
            #pragma unroll
            for (int r = 0; r < 4; r++) {
                uint32_t* pa = &AS(nxt, (r << 5) + ldr, stc);
                uint32_t* pb = &BS(nxt, (r << 5) + ldr, stc);
                pa[0] = f2tf(av[r].x); pa[2] = f2tf(av[r].y); pa[4] = f2tf(av[r].z); pa[6] = f2tf(av[r].w);
                pb[0] = f2tf(bv[r].x); pb[2] = f2tf(bv[r].y); pb[4] = f2tf(bv[r].z); pb[6] = f2tf(bv[r].w);
            }
            __syncthreads();
        }
        cur ^= 1;
    }

    #pragma unroll
    for (int im = 0; im < 4; im++)
        #pragma unroll
        for (int jn = 0; jn < 4; jn++)
            #pragma unroll
            for (int e = 0; e < 4; e++) {
                int m = m0 + wm + (im << 4) + g4 + ((e >> 1) << 3);
                int n = n0 + wn + (jn << 3) + (g1 << 1) + (e & 1);
                float v = acc[im][jn][e] + bias[n];
                if (EPI == 0) {
                    int t = m >> 2, bb = m & 3;
                    int c = n >> 10;
                    int ee = n & 1023;
                    int h = ee >> 6, d = ee & 63;
                    int idx = (((bb << 4) + h) * TLEN + t) * HD + d;
                    if (c == 0)      g_Q[idx] = v * QSCALE;
                    else if (c == 1) g_K[idx] = v;
                    else             g_V[idx] = v;
                } else {
                    C[(size_t)m * EMBED + n] = v;
                }
            }
}

// ---------------------------------------------------------------------------
// Fused flash attention (from R8, proven) with paired-column smem layout.
// ---------------------------------------------------------------------------
#define ATT_OFF_Q   0
#define ATT_OFF_K   8704
#define ATT_OFF_V   13056
#define ATT_OFF_P   17408
#define ATT_OFF_RED 26112
#define ATT_OFF_MT  27136
#define ATT_OFF_PAD 29184
#define ATT_SMEM_WORDS 29248

__global__ __launch_bounds__(256) void k_attn(const int* __restrict__ pad) {
    extern __shared__ uint32_t sm[];
    uint32_t* Qs = sm + ATT_OFF_Q;
    uint32_t* Ks = sm + ATT_OFF_K;
    uint32_t* Vs = sm + ATT_OFF_V;
    uint32_t* Ps = sm + ATT_OFF_P;
    float* redm = (float*)(sm + ATT_OFF_RED);
    float* reds = redm + 512;
    float* mtl  = (float*)(sm + ATT_OFF_MT);
    int*   pads = (int*)(sm + ATT_OFF_PAD);

    const int bh = blockIdx.y;
    const int t0 = (7 - blockIdx.x) << 7;
    const int b  = bh >> 4;
    const int h  = bh & 15;
    const int tid  = threadIdx.x;
    const int lane = tid & 31;
    const int wid  = tid >> 5;
    const int wm = (wid & 1) << 6;
    const int wn = (wid >> 1) << 4;
    const int g4 = lane >> 2;
    const int g1 = lane & 3;
    const int wc = wid >> 1;

    const float* Qg = g_Q + (size_t)bh * TLEN * HD;
    const float* Kg = g_K + (size_t)bh * TLEN * HD;
    const float* Vg = g_V + (size_t)bh * TLEN * HD;
    float* Pg = g_P + (size_t)bh * TLEN * TLEN;

    // Q tile 128x64 -> smem (tf32, permuted columns)
    {
        int qr = tid >> 1;
        int qc = (tid & 1) << 5;
        #pragma unroll
        for (int j = 0; j < 8; j++) {
            float4 q = *(const float4*)(Qg + (size_t)(t0 + qr) * HD + qc + j * 4);
            uint32_t* p = &Qs[qr * 68 + qc + ((j >> 1) << 3) + (j & 1)];
            p[0] = f2tf(q.x); p[2] = f2tf(q.y); p[4] = f2tf(q.z); p[6] = f2tf(q.w);
        }
    }

    float m_run[4][2], l_run[4][2];
    float acc_o[4][2][4] = {};
    #pragma unroll
    for (int im = 0; im < 4; im++) {
        m_run[im][0] = m_run[im][1] = -1e30f;
        l_run[im][0] = l_run[im][1] = 0.f;
    }
    __syncthreads();

    const int nt = (t0 + 128) >> 6;
    const int kr = tid >> 2;
    const int krp = (kr & 56) | (((kr & 3) << 1) | ((kr >> 2) & 1));  // permuted s-col for V
    const int kc = (tid & 3) << 4;

    for (int it = 0; it < nt; it++) {
        const int s0 = it << 6;
        float4 kf[4], vf[4];
        #pragma unroll
        for (int j = 0; j < 4; j++) {
            kf[j] = *(const float4*)(Kg + (size_t)(s0 + kr) * HD + kc + j * 4);
            vf[j] = *(const float4*)(Vg + (size_t)(s0 + kr) * HD + kc + j * 4);
        }
        int padv = (tid < 64) ? pad[b * TLEN + s0 + tid] : 0;
        __syncthreads();
        #pragma unroll
        for (int j = 0; j < 4; j++) {
            uint32_t* p = &Ks[kr * 68 + kc + ((j >> 1) << 3) + (j & 1)];
            p[0] = f2tf(kf[j].x); p[2] = f2tf(kf[j].y); p[4] = f2tf(kf[j].z); p[6] = f2tf(kf[j].w);
            Vs[(kc + j * 4 + 0) * 68 + krp] = f2tf(vf[j].x);
            Vs[(kc + j * 4 + 1) * 68 + krp] = f2tf(vf[j].y);
            Vs[(kc + j * 4 + 2) * 68 + krp] = f2tf(vf[j].z);
            Vs[(kc + j * 4 + 3) * 68 + krp] = f2tf(vf[j].w);
        }
        if (tid < 64) pads[tid] = padv;
        __syncthreads();

        // ---- S = Q K^T ----
        float accs[4][2][4] = {};
        #pragma unroll
        for (int kk = 0; kk < 64; kk += 8) {
            const int pc = kk + (g1 << 1);
            uint32_t a[4][4], bf[2][2];
            #pragma unroll
            for (int im = 0; im < 4; im++) {
                int mr = wm + (im << 4) + g4;
                uint2 lo = *(const uint2*)&Qs[mr * 68 + pc];
                uint2 hi = *(const uint2*)&Qs[(mr + 8) * 68 + pc];
                a[im][0] = lo.x; a[im][1] = hi.x; a[im][2] = lo.y; a[im][3] = hi.y;
            }
            #pragma unroll
            for (int jn = 0; jn < 2; jn++) {
                int nr = wn + (jn << 3) + g4;
                uint2 bb = *(const uint2*)&Ks[nr * 68 + pc];
                bf[jn][0] = bb.x; bf[jn][1] = bb.y;
            }
            #pragma unroll
            for (int im = 0; im < 4; im++)
                #pragma unroll
                for (int jn = 0; jn < 2; jn++)
                    mma_tf32(accs[im][jn], a[im], bf[jn]);
        }

        // ---- mask + tile row max ----
        float mloc[4][2];
        #pragma unroll
        for (int im = 0; im < 4; im++)
            #pragma unroll
            for (int ep = 0; ep < 2; ep++) {
                int t = t0 + wm + (im << 4) + g4 + (ep << 3);
                float mm = -1e30f;
                #pragma unroll
                for (int jn = 0; jn < 2; jn++)
                    #pragma unroll
                    for (int c = 0; c < 2; c++) {
                        int s = s0 + wn + (jn << 3) + (g1 << 1) + c;
                        bool ok = (s <= t) && (pads[s - s0] == 0);
                        float v = ok ? accs[im][jn][(ep << 1) + c] : -1e30f;
                        accs[im][jn][(ep << 1) + c] = v;
                        mm = fmaxf(mm, v);
                    }
                mm = fmaxf(mm, __shfl_xor_sync(0xffffffffu, mm, 1));
                mm = fmaxf(mm, __shfl_xor_sync(0xffffffffu, mm, 2));
                mloc[im][ep] = mm;
            }
        if (g1 == 0) {
            #pragma unroll
            for (int im = 0; im < 4; im++)
                #pragma unroll
                for (int ep = 0; ep < 2; ep++)
                    redm[wc * 128 + wm + (im << 4) + g4 + (ep << 3)] = mloc[im][ep];
        }
        __syncthreads();

        // ---- combine max, rescale ----
        float m_new[4][2];
        #pragma unroll
        for (int im = 0; im < 4; im++)
            #pragma unroll
            for (int ep = 0; ep < 2; ep++) {
                int row = wm + (im << 4) + g4 + (ep << 3);
                float mt = fmaxf(fmaxf(redm[row], redm[128 + row]),
                                 fmaxf(redm[256 + row], redm[384 + row]));
                float mn = fmaxf(m_run[im][ep], mt);
                float f = __expf(m_run[im][ep] - mn);
                m_new[im][ep] = mn;
                m_run[im][ep] = mn;
                l_run[im][ep] *= f;
                #pragma unroll
                for (int jn = 0; jn < 2; jn++) {
                    acc_o[im][jn][(ep << 1) + 0] *= f;
                    acc_o[im][jn][(ep << 1) + 1] *= f;
                }
                if (wc == 0 && g1 == 0) mtl[row * 16 + it] = mn;
            }

        // ---- p = exp, write gmem + smem(permuted), row sums ----
        #pragma unroll
        for (int im = 0; im < 4; im++)
            #pragma unroll
            for (int ep = 0; ep < 2; ep++) {
                int t = t0 + wm + (im << 4) + g4 + (ep << 3);
                int rowL = t - t0;
                float ssum = 0.f;
                #pragma unroll
                for (int jn = 0; jn < 2; jn++) {
                    int cb = wn + (jn << 3) + (g1 << 1);
                    float p0 = __expf(accs[im][jn][(ep << 1) + 0] - m_new[im][ep]);
                    float p1 = __expf(accs[im][jn][(ep << 1) + 1] - m_new[im][ep]);
                    ssum += p0 + p1;
                    *(float2*)(Pg + (size_t)t * TLEN + s0 + cb) = make_float2(p0, p1);
                    Ps[rowL * 68 + perm8c(cb)]     = f2tf(p0);
                    Ps[rowL * 68 + perm8c(cb + 1)] = f2tf(p1);
                }
                ssum += __shfl_xor_sync(0xffffffffu, ssum, 1);
                ssum += __shfl_xor_sync(0xffffffffu, ssum, 2);
                if (g1 == 0) reds[wc * 128 + rowL] = ssum;
            }
        __syncthreads();
        #pragma unroll
        for (int im = 0; im < 4; im++)
            #pragma unroll
            for (int ep = 0; ep < 2; ep++) {
                int row = wm + (im << 4) + g4 + (ep << 3);
                l_run[im][ep] += reds[row] + reds[128 + row] + reds[256 + row] + reds[384 + row];
            }

        // ---- O += P~ V ----
        #pragma unroll
        for (int kk = 0; kk < 64; kk += 8) {
            const int pc = kk + (g1 << 1);
            uint32_t a[4][4], bf[2][2];
            #pragma unroll
            for (int im = 0; im < 4; im++) {
                int mr = wm + (im << 4) + g4;
                uint2 lo = *(const uint2*)&Ps[mr * 68 + pc];
                uint2 hi = *(const uint2*)&Ps[(mr + 8) * 68 + pc];
                a[im][0] = lo.x; a[im][1] = hi.x; a[im][2] = lo.y; a[im][3] = hi.y;
            }
            #pragma unroll
            for (int jn = 0; jn < 2; jn++) {
                int nr = wn + (jn << 3) + g4;
                uint2 bb = *(const uint2*)&Vs[nr * 68 + pc];
                bf[jn][0] = bb.x; bf[jn][1] = bb.y;
            }
            #pragma unroll
            for (int im = 0; im < 4; im++)
                #pragma unroll
                for (int jn = 0; jn < 2; jn++)
                    mma_tf32(acc_o[im][jn], a[im], bf[jn]);
        }
    }

    // ---- epilogue ----
    #pragma unroll
    for (int im = 0; im < 4; im++)
        #pragma unroll
        for (int ep = 0; ep < 2; ep++) {
            int t = t0 + wm + (im << 4) + g4 + (ep << 3);
            float inv = 1.f / l_run[im][ep];
            #pragma unroll
            for (int jn = 0; jn < 2; jn++) {
                int d = wn + (jn << 3) + (g1 << 1);
                float* o = g_A + ((size_t)t * BATCH + b) * EMBED + (h << 6) + d;
                *(float2*)o = make_float2(acc_o[im][jn][(ep << 1) + 0] * inv,
                                          acc_o[im][jn][(ep << 1) + 1] * inv);
            }
        }
    if (wc == 0 && g1 == 0) {
        #pragma unroll
        for (int im = 0; im < 4; im++)
            #pragma unroll
            for (int ep = 0; ep < 2; ep++) {
                int row = wm + (im << 4) + g4 + (ep << 3);
                int t = t0 + row;
                float inv = 1.f / l_run[im][ep];
                float mfin = m_run[im][ep];
                for (int it2 = 0; it2 < nt; it2++) {
                    float c = __expf(mtl[row * 16 + it2] - mfin) * inv;
                    g_C[((size_t)bh * TLEN + t) * 16 + it2] = c;
                }
            }
    }
}

// ---------------------------------------------------------------------------
// avg_weights[b,t,s] = (1/16) sum_h P~[bh,t,s] * C[bh,t,s>>6]; 0 for s>t.
// ---------------------------------------------------------------------------
__global__ __launch_bounds__(256) void k_avg(float* __restrict__ outAvg) {
    const int idx = blockIdx.x * 256 + threadIdx.x;
    const int s = idx & 1023;
    const int t = (idx >> 10) & 1023;
    const int b = idx >> 20;
    if (s > t) { outAvg[idx] = 0.f; return; }
    const int tile = s >> 6;
    float sum = 0.f;
    #pragma unroll
    for (int h = 0; h < 16; h++) {
        size_t base = (size_t)((b << 4) + h) * TLEN + t;
        sum += g_P[base * TLEN + s] * g_C[base * 16 + tile];
    }
    outAvg[idx] = sum * 0.0625f;
}

// ---------------------------------------------------------------------------
extern "C" void kernel_launch(void* const* d_in, const int* in_sizes, int n_in,
                              void* d_out, int out_size) {
    const float* query = (const float*)d_in[0];
    const int*   mask  = (const int*)d_in[1];   // numpy bool widened to int32
    const float* w_in  = (const float*)d_in[2];
    const float* b_in  = (const float*)d_in[3];
    const float* w_out = (const float*)d_in[4];
    const float* b_out = (const float*)d_in[5];

    float* outAttn = (float*)d_out;                                   // [T,B,E]
    float* outAvg  = (float*)d_out + (size_t)MROWS * EMBED;           // [B,T,S]

    static cudaStream_t s_avg = nullptr;
    static cudaEvent_t ev_fork = nullptr, ev_join = nullptr;
    if (s_avg == nullptr) {
        cudaStreamCreateWithFlags(&s_avg, cudaStreamNonBlocking);
        cudaEventCreateWithFlags(&ev_fork, cudaEventDisableTiming);
        cudaEventCreateWithFlags(&ev_join, cudaEventDisableTiming);
    }

    const int gemm_smem = GEMM_SMEM_WORDS * 4;
    const int attn_smem = ATT_SMEM_WORDS * 4;
    cudaFuncSetAttribute(k_gemm_tf32<0>, cudaFuncAttributeMaxDynamicSharedMemorySize, gemm_smem);
    cudaFuncSetAttribute(k_gemm_tf32<1>, cudaFuncAttributeMaxDynamicSharedMemorySize, gemm_smem);
    cudaFuncSetAttribute(k_attn,         cudaFuncAttributeMaxDynamicSharedMemorySize, attn_smem);

    k_gemm_tf32<0><<<dim3(24, 32), 256, gemm_smem>>>(query, w_in, b_in, nullptr, EMBED);
    k_attn<<<dim3(8, 64), 256, attn_smem>>>(mask);

    cudaEventRecord(ev_fork, 0);
    cudaStreamWaitEvent(s_avg, ev_fork, 0);
    k_avg<<<16384, 256, 0, s_avg>>>(outAvg);
    cudaEventRecord(ev_join, s_avg);

    k_gemm_tf32<1><<<dim3(8, 32), 256, gemm_smem>>>(nullptr, w_out, b_out, outAttn, EMBED);

    cudaStreamWaitEvent(0, ev_join, 0);
}

// round 10
// speedup vs baseline: 1.2056x; 1.2056x over previous
#include <cuda_runtime.h>
#include <math.h>
#include <stdint.h>

#define TLEN   1024
#define BATCH  4
#define EMBED  1024
#define NH     16
#define HD     64
#define QSCALE 0.125f
#define MROWS  (TLEN * BATCH)   // 4096

// Scratch (static device globals — no cudaMalloc anywhere)
__device__ float g_Q[BATCH * NH * TLEN * HD];                 // [b,h,t,d], pre-scaled
__device__ float g_K[BATCH * NH * TLEN * HD];
__device__ float g_V[BATCH * NH * TLEN * HD];
__device__ float g_P[(size_t)BATCH * NH * TLEN * TLEN];       // unnormalized exp tiles
__device__ float g_C[BATCH * NH * TLEN * 16];                 // per-(row,tile) corrections
__device__ float g_M[BATCH * NH * TLEN * 16];                 // per-(row,tile) running max
__device__ float g_A[MROWS * EMBED];                          // attention context [t,b,e]

__device__ __forceinline__ uint32_t f2tf(float f) {
    uint32_t u;
    asm("cvt.rna.tf32.f32 %0, %1;" : "=r"(u) : "f"(f));
    return u;
}

__device__ __forceinline__ void mma_tf32(float* d, const uint32_t* a, const uint32_t* b) {
    asm volatile(
        "mma.sync.aligned.m16n8k8.row.col.f32.tf32.tf32.f32 "
        "{%0,%1,%2,%3}, {%4,%5,%6,%7}, {%8,%9}, {%0,%1,%2,%3};"
        : "+f"(d[0]), "+f"(d[1]), "+f"(d[2]), "+f"(d[3])
        : "r"(a[0]), "r"(a[1]), "r"(a[2]), "r"(a[3]), "r"(b[0]), "r"(b[1]));
}

// ---------------------------------------------------------------------------
// TF32 tensor-core GEMM (R8 layout — conflict-free LDS.32 fragments)
// ---------------------------------------------------------------------------
#define GEMM_SMEM_WORDS (4 * 128 * 36)
#define AS(buf, r, c) As[(buf) * 4608 + (r) * 36 + (c)]
#define BS(buf, r, c) Bs[(buf) * 4608 + (r) * 36 + (c)]

template <int EPI>
__global__ __launch_bounds__(256) void k_gemm_tf32(const float* __restrict__ Ain,
                                                   const float* __restrict__ B,
                                                   const float* __restrict__ bias,
                                                   float* __restrict__ C,
                                                   int K) {
    const float* A = (EPI == 0) ? Ain : (const float*)g_A;
    extern __shared__ uint32_t smraw[];
    uint32_t* As = smraw;
    uint32_t* Bs = smraw + 2 * 4608;
    const int tid  = threadIdx.x;
    const int lane = tid & 31;
    const int wid  = tid >> 5;
    const int wm   = (wid & 1) << 6;
    const int wn   = (wid >> 1) << 5;
    const int m0   = blockIdx.y << 7;
    const int n0   = blockIdx.x << 7;
    const int ldr = tid >> 3;
    const int ldc = (tid & 7) << 2;
    const int g4 = lane >> 2;
    const int g1 = lane & 3;

    float acc[4][4][4] = {};
    float4 av[4], bv[4];

    const float* Abase = A + (size_t)(m0 + ldr) * K + ldc;
    const float* Bbase = B + (size_t)(n0 + ldr) * K + ldc;

    #pragma unroll
    for (int r = 0; r < 4; r++) {
        av[r] = *(const float4*)(Abase + (size_t)(r << 5) * K);
        bv[r] = *(const float4*)(Bbase + (size_t)(r << 5) * K);
    }
    #pragma unroll
    for (int r = 0; r < 4; r++) {
        uint32_t* pa = &AS(0, (r << 5) + ldr, ldc);
        uint32_t* pb = &BS(0, (r << 5) + ldr, ldc);
        pa[0] = f2tf(av[r].x); pa[1] = f2tf(av[r].y); pa[2] = f2tf(av[r].z); pa[3] = f2tf(av[r].w);
        pb[0] = f2tf(bv[r].x); pb[1] = f2tf(bv[r].y); pb[2] = f2tf(bv[r].z); pb[3] = f2tf(bv[r].w);
    }
    __syncthreads();

    int cur = 0;
    for (int k0 = 0; k0 < K; k0 += 32) {
        const bool has_next = (k0 + 32 < K);
        if (has_next) {
            #pragma unroll
            for (int r = 0; r < 4; r++) {
                av[r] = *(const float4*)(Abase + (size_t)(r << 5) * K + k0 + 32);
                bv[r] = *(const float4*)(Bbase + (size_t)(r << 5) * K + k0 + 32);
            }
        }
        #pragma unroll
        for (int kk = 0; kk < 32; kk += 8) {
            uint32_t a[4][4], b[4][2];
            #pragma unroll
            for (int im = 0; im < 4; im++) {
                int mr = wm + (im << 4) + g4;
                a[im][0] = AS(cur, mr    , kk + g1    );
                a[im][1] = AS(cur, mr + 8, kk + g1    );
                a[im][2] = AS(cur, mr    , kk + g1 + 4);
                a[im][3] = AS(cur, mr + 8, kk + g1 + 4);
            }
            #pragma unroll
            for (int jn = 0; jn < 4; jn++) {
                int nr = wn + (jn << 3) + g4;
                b[jn][0] = BS(cur, nr, kk + g1    );
                b[jn][1] = BS(cur, nr, kk + g1 + 4);
            }
            #pragma unroll
            for (int im = 0; im < 4; im++)
                #pragma unroll
                for (int jn = 0; jn < 4; jn++)
                    mma_tf32(acc[im][jn], a[im], b[jn]);
        }
        if (has_next) {
            int nxt = cur ^ 1;
            #pragma unroll
            for (int r = 0; r < 4; r++) {
                uint32_t* pa = &AS(nxt, (r << 5) + ldr, ldc);
                uint32_t* pb = &BS(nxt, (r << 5) + ldr, ldc);
                pa[0] = f2tf(av[r].x); pa[1] = f2tf(av[r].y); pa[2] = f2tf(av[r].z); pa[3] = f2tf(av[r].w);
                pb[0] = f2tf(bv[r].x); pb[1] = f2tf(bv[r].y); pb[2] = f2tf(bv[r].z); pb[3] = f2tf(bv[r].w);
            }
            __syncthreads();
        }
        cur ^= 1;
    }

    #pragma unroll
    for (int im = 0; im < 4; im++)
        #pragma unroll
        for (int jn = 0; jn < 4; jn++)
            #pragma unroll
            for (int e = 0; e < 4; e++) {
                int m = m0 + wm + (im << 4) + g4 + ((e >> 1) << 3);
                int n = n0 + wn + (jn << 3) + (g1 << 1) + (e & 1);
                float v = acc[im][jn][e] + bias[n];
                if (EPI == 0) {
                    int t = m >> 2, bb = m & 3;
                    int c = n >> 10;
                    int ee = n & 1023;
                    int h = ee >> 6, d = ee & 63;
                    int idx = (((bb << 4) + h) * TLEN + t) * HD + d;
                    if (c == 0)      g_Q[idx] = v * QSCALE;
                    else if (c == 1) g_K[idx] = v;
                    else             g_V[idx] = v;
                } else {
                    C[(size_t)m * EMBED + n] = v;
                }
            }
}

// ---------------------------------------------------------------------------
// Fused flash attention (R8 layout). m_tile table moved to GLOBAL scratch so
// smem = 108,800 B < 114 KB -> 2 CTAs/SM (was 116,992 B -> 1 CTA/SM).
// ---------------------------------------------------------------------------
#define ATT_OFF_Q   0            // 128x68 words
#define ATT_OFF_K   8704         // 64x68
#define ATT_OFF_V   13056        // 64x68 (transposed: [d][s])
#define ATT_OFF_P   17408        // 128x68
#define ATT_OFF_RED 26112        // redm[4][128] + reds[4][128]
#define ATT_OFF_PAD 27136        // 64 ints
#define ATT_SMEM_WORDS 27200

__global__ __launch_bounds__(256, 2) void k_attn(const int* __restrict__ pad) {
    extern __shared__ uint32_t sm[];
    uint32_t* Qs = sm + ATT_OFF_Q;
    uint32_t* Ks = sm + ATT_OFF_K;
    uint32_t* Vs = sm + ATT_OFF_V;
    uint32_t* Ps = sm + ATT_OFF_P;
    float* redm = (float*)(sm + ATT_OFF_RED);
    float* reds = redm + 512;
    int*   pads = (int*)(sm + ATT_OFF_PAD);

    const int bh = blockIdx.y;
    const int t0 = (7 - blockIdx.x) << 7;      // big tiles first
    const int b  = bh >> 4;
    const int h  = bh & 15;
    const int tid  = threadIdx.x;
    const int lane = tid & 31;
    const int wid  = tid >> 5;
    const int wm = (wid & 1) << 6;
    const int wn = (wid >> 1) << 4;
    const int g4 = lane >> 2;
    const int g1 = lane & 3;
    const int wc = wid >> 1;

    const float* Qg = g_Q + (size_t)bh * TLEN * HD;
    const float* Kg = g_K + (size_t)bh * TLEN * HD;
    const float* Vg = g_V + (size_t)bh * TLEN * HD;
    float* Pg = g_P + (size_t)bh * TLEN * TLEN;

    // Q tile 128x64 -> smem (tf32)
    {
        int qr = tid >> 1;
        int qc = (tid & 1) << 5;
        #pragma unroll
        for (int j = 0; j < 8; j++) {
            float4 q = *(const float4*)(Qg + (size_t)(t0 + qr) * HD + qc + j * 4);
            uint32_t* p = &Qs[qr * 68 + qc + j * 4];
            p[0] = f2tf(q.x); p[1] = f2tf(q.y); p[2] = f2tf(q.z); p[3] = f2tf(q.w);
        }
    }

    float m_run[4][2], l_run[4][2];
    float acc_o[4][2][4] = {};
    #pragma unroll
    for (int im = 0; im < 4; im++) {
        m_run[im][0] = m_run[im][1] = -1e30f;
        l_run[im][0] = l_run[im][1] = 0.f;
    }
    __syncthreads();

    const int nt = (t0 + 128) >> 6;   // 2..16 tiles of 64
    const int kr = tid >> 2;
    const int kc = (tid & 3) << 4;

    for (int it = 0; it < nt; it++) {
        const int s0 = it << 6;
        float4 kf[4], vf[4];
        #pragma unroll
        for (int j = 0; j < 4; j++) {
            kf[j] = *(const float4*)(Kg + (size_t)(s0 + kr) * HD + kc + j * 4);
            vf[j] = *(const float4*)(Vg + (size_t)(s0 + kr) * HD + kc + j * 4);
        }
        int padv = (tid < 64) ? pad[b * TLEN + s0 + tid] : 0;
        __syncthreads();                       // prev tile's smem consumed
        #pragma unroll
        for (int j = 0; j < 4; j++) {
            uint32_t* p = &Ks[kr * 68 + kc + j * 4];
            p[0] = f2tf(kf[j].x); p[1] = f2tf(kf[j].y); p[2] = f2tf(kf[j].z); p[3] = f2tf(kf[j].w);
            Vs[(kc + j * 4 + 0) * 68 + kr] = f2tf(vf[j].x);
            Vs[(kc + j * 4 + 1) * 68 + kr] = f2tf(vf[j].y);
            Vs[(kc + j * 4 + 2) * 68 + kr] = f2tf(vf[j].z);
            Vs[(kc + j * 4 + 3) * 68 + kr] = f2tf(vf[j].w);
        }
        if (tid < 64) pads[tid] = padv;
        __syncthreads();

        // ---- S = Q K^T  (128x64, K=64) ----
        float accs[4][2][4] = {};
        #pragma unroll
        for (int kk = 0; kk < 64; kk += 8) {
            uint32_t a[4][4], bf[2][2];
            #pragma unroll
            for (int im = 0; im < 4; im++) {
                int mr = wm + (im << 4) + g4;
                a[im][0] = Qs[mr * 68 + kk + g1];
                a[im][1] = Qs[(mr + 8) * 68 + kk + g1];
                a[im][2] = Qs[mr * 68 + kk + g1 + 4];
                a[im][3] = Qs[(mr + 8) * 68 + kk + g1 + 4];
            }
            #pragma unroll
            for (int jn = 0; jn < 2; jn++) {
                int nr = wn + (jn << 3) + g4;
                bf[jn][0] = Ks[nr * 68 + kk + g1];
                bf[jn][1] = Ks[nr * 68 + kk + g1 + 4];
            }
            #pragma unroll
            for (int im = 0; im < 4; im++)
                #pragma unroll
                for (int jn = 0; jn < 2; jn++)
                    mma_tf32(accs[im][jn], a[im], bf[jn]);
        }

        // ---- mask + tile row max ----
        float mloc[4][2];
        #pragma unroll
        for (int im = 0; im < 4; im++)
            #pragma unroll
            for (int ep = 0; ep < 2; ep++) {
                int t = t0 + wm + (im << 4) + g4 + (ep << 3);
                float mm = -1e30f;
                #pragma unroll
                for (int jn = 0; jn < 2; jn++)
                    #pragma unroll
                    for (int c = 0; c < 2; c++) {
                        int s = s0 + wn + (jn << 3) + (g1 << 1) + c;
                        bool ok = (s <= t) && (pads[s - s0] == 0);
                        float v = ok ? accs[im][jn][(ep << 1) + c] : -1e30f;
                        accs[im][jn][(ep << 1) + c] = v;
                        mm = fmaxf(mm, v);
                    }
                mm = fmaxf(mm, __shfl_xor_sync(0xffffffffu, mm, 1));
                mm = fmaxf(mm, __shfl_xor_sync(0xffffffffu, mm, 2));
                mloc[im][ep] = mm;
            }
        if (g1 == 0) {
            #pragma unroll
            for (int im = 0; im < 4; im++)
                #pragma unroll
                for (int ep = 0; ep < 2; ep++)
                    redm[wc * 128 + wm + (im << 4) + g4 + (ep << 3)] = mloc[im][ep];
        }
        __syncthreads();

        // ---- combine max, rescale ----
        float m_new[4][2];
        #pragma unroll
        for (int im = 0; im < 4; im++)
            #pragma unroll
            for (int ep = 0; ep < 2; ep++) {
                int row = wm + (im << 4) + g4 + (ep << 3);
                float mt = fmaxf(fmaxf(redm[row], redm[128 + row]),
                                 fmaxf(redm[256 + row], redm[384 + row]));
                float mn = fmaxf(m_run[im][ep], mt);
                float f = __expf(m_run[im][ep] - mn);
                m_new[im][ep] = mn;
                m_run[im][ep] = mn;
                l_run[im][ep] *= f;
                #pragma unroll
                for (int jn = 0; jn < 2; jn++) {
                    acc_o[im][jn][(ep << 1) + 0] *= f;
                    acc_o[im][jn][(ep << 1) + 1] *= f;
                }
                if (wc == 0 && g1 == 0)
                    g_M[((size_t)bh * TLEN + t0 + row) * 16 + it] = mn;
            }

        // ---- p = exp, write gmem + smem, row sums ----
        #pragma unroll
        for (int im = 0; im < 4; im++)
            #pragma unroll
            for (int ep = 0; ep < 2; ep++) {
                int t = t0 + wm + (im << 4) + g4 + (ep << 3);
                int rowL = t - t0;
                float ssum = 0.f;
                #pragma unroll
                for (int jn = 0; jn < 2; jn++) {
                    int cb = wn + (jn << 3) + (g1 << 1);
                    float p0 = __expf(accs[im][jn][(ep << 1) + 0] - m_new[im][ep]);
                    float p1 = __expf(accs[im][jn][(ep << 1) + 1] - m_new[im][ep]);
                    ssum += p0 + p1;
                    *(float2*)(Pg + (size_t)t * TLEN + s0 + cb) = make_float2(p0, p1);
                    Ps[rowL * 68 + cb]     = f2tf(p0);
                    Ps[rowL * 68 + cb + 1] = f2tf(p1);
                }
                ssum += __shfl_xor_sync(0xffffffffu, ssum, 1);
                ssum += __shfl_xor_sync(0xffffffffu, ssum, 2);
                if (g1 == 0) reds[wc * 128 + rowL] = ssum;
            }
        __syncthreads();
        #pragma unroll
        for (int im = 0; im < 4; im++)
            #pragma unroll
            for (int ep = 0; ep < 2; ep++) {
                int row = wm + (im << 4) + g4 + (ep << 3);
                l_run[im][ep] += reds[row] + reds[128 + row] + reds[256 + row] + reds[384 + row];
            }

        // ---- O += P~ V  (128x64, K=64) ----
        #pragma unroll
        for (int kk = 0; kk < 64; kk += 8) {
            uint32_t a[4][4], bf[2][2];
            #pragma unroll
            for (int im = 0; im < 4; im++) {
                int mr = wm + (im << 4) + g4;
                a[im][0] = Ps[mr * 68 + kk + g1];
                a[im][1] = Ps[(mr + 8) * 68 + kk + g1];
                a[im][2] = Ps[mr * 68 + kk + g1 + 4];
                a[im][3] = Ps[(mr + 8) * 68 + kk + g1 + 4];
            }
            #pragma unroll
            for (int jn = 0; jn < 2; jn++) {
                int nr = wn + (jn << 3) + g4;
                bf[jn][0] = Vs[nr * 68 + kk + g1];
                bf[jn][1] = Vs[nr * 68 + kk + g1 + 4];
            }
            #pragma unroll
            for (int im = 0; im < 4; im++)
                #pragma unroll
                for (int jn = 0; jn < 2; jn++)
                    mma_tf32(acc_o[im][jn], a[im], bf[jn]);
        }
    }

    // ---- epilogue: O/l -> g_A; corrections -> g_C (reads m-table from g_M) ----
    #pragma unroll
    for (int im = 0; im < 4; im++)
        #pragma unroll
        for (int ep = 0; ep < 2; ep++) {
            int t = t0 + wm + (im << 4) + g4 + (ep << 3);
            float inv = 1.f / l_run[im][ep];
            #pragma unroll
            for (int jn = 0; jn < 2; jn++) {
                int d = wn + (jn << 3) + (g1 << 1);
                float* o = g_A + ((size_t)t * BATCH + b) * EMBED + (h << 6) + d;
                *(float2*)o = make_float2(acc_o[im][jn][(ep << 1) + 0] * inv,
                                          acc_o[im][jn][(ep << 1) + 1] * inv);
            }
        }
    if (wc == 0 && g1 == 0) {
        #pragma unroll
        for (int im = 0; im < 4; im++)
            #pragma unroll
            for (int ep = 0; ep < 2; ep++) {
                int row = wm + (im << 4) + g4 + (ep << 3);
                int t = t0 + row;
                float inv = 1.f / l_run[im][ep];
                float mfin = m_run[im][ep];
                for (int it2 = 0; it2 < nt; it2++) {
                    float mv = g_M[((size_t)bh * TLEN + t) * 16 + it2];
                    g_C[((size_t)bh * TLEN + t) * 16 + it2] = __expf(mv - mfin) * inv;
                }
            }
    }
}

// ---------------------------------------------------------------------------
// avg_weights[b,t,s] = (1/16) sum_h P~[bh,t,s] * C[bh,t,s>>6]; 0 for s>t.
// ---------------------------------------------------------------------------
__global__ __launch_bounds__(256) void k_avg(float* __restrict__ outAvg) {
    const int idx = blockIdx.x * 256 + threadIdx.x;
    const int s = idx & 1023;
    const int t = (idx >> 10) & 1023;
    const int b = idx >> 20;
    if (s > t) { outAvg[idx] = 0.f; return; }
    const int tile = s >> 6;
    float sum = 0.f;
    #pragma unroll
    for (int h = 0; h < 16; h++) {
        size_t base = (size_t)((b << 4) + h) * TLEN + t;
        sum += g_P[base * TLEN + s] * g_C[base * 16 + tile];
    }
    outAvg[idx] = sum * 0.0625f;
}

// ---------------------------------------------------------------------------
extern "C" void kernel_launch(void* const* d_in, const int* in_sizes, int n_in,
                              void* d_out, int out_size) {
    const float* query = (const float*)d_in[0];
    const int*   mask  = (const int*)d_in[1];   // numpy bool widened to int32
    const float* w_in  = (const float*)d_in[2];
    const float* b_in  = (const float*)d_in[3];
    const float* w_out = (const float*)d_in[4];
    const float* b_out = (const float*)d_in[5];

    float* outAttn = (float*)d_out;                                   // [T,B,E]
    float* outAvg  = (float*)d_out + (size_t)MROWS * EMBED;           // [B,T,S]

    static cudaStream_t s_avg = nullptr;
    static cudaEvent_t ev_fork = nullptr, ev_join = nullptr;
    if (s_avg == nullptr) {
        cudaStreamCreateWithFlags(&s_avg, cudaStreamNonBlocking);
        cudaEventCreateWithFlags(&ev_fork, cudaEventDisableTiming);
        cudaEventCreateWithFlags(&ev_join, cudaEventDisableTiming);
    }

    const int gemm_smem = GEMM_SMEM_WORDS * 4;   // 73,728 B
    const int attn_smem = ATT_SMEM_WORDS * 4;    // 108,800 B -> 2 CTAs/SM
    cudaFuncSetAttribute(k_gemm_tf32<0>, cudaFuncAttributeMaxDynamicSharedMemorySize, gemm_smem);
    cudaFuncSetAttribute(k_gemm_tf32<1>, cudaFuncAttributeMaxDynamicSharedMemorySize, gemm_smem);
    cudaFuncSetAttribute(k_attn,         cudaFuncAttributeMaxDynamicSharedMemorySize, attn_smem);

    k_gemm_tf32<0><<<dim3(24, 32), 256, gemm_smem>>>(query, w_in, b_in, nullptr, EMBED);
    k_attn<<<dim3(8, 64), 256, attn_smem>>>(mask);

    cudaEventRecord(ev_fork, 0);
    cudaStreamWaitEvent(s_avg, ev_fork, 0);
    k_avg<<<16384, 256, 0, s_avg>>>(outAvg);
    cudaEventRecord(ev_join, s_avg);

    k_gemm_tf32<1><<<dim3(8, 32), 256, gemm_smem>>>(nullptr, w_out, b_out, outAttn, EMBED);

    cudaStreamWaitEvent(0, ev_join, 0);
}

// round 11
// speedup vs baseline: 1.2593x; 1.0446x over previous
#include <cuda_runtime.h>
#include <math.h>
#include <stdint.h>

#define TLEN   1024
#define BATCH  4
#define EMBED  1024
#define NH     16
#define HD     64
#define QSCALE 0.125f
#define MROWS  (TLEN * BATCH)   // 4096

// Scratch (static device globals — no cudaMalloc anywhere)
__device__ float g_Q[BATCH * NH * TLEN * HD];                 // [b,h,t,d], pre-scaled
__device__ float g_K[BATCH * NH * TLEN * HD];
__device__ float g_V[BATCH * NH * TLEN * HD];
__device__ float g_P[(size_t)BATCH * NH * TLEN * TLEN];       // unnormalized exp tiles
__device__ float g_C[BATCH * NH * TLEN * 16];                 // per-(row,tile) corrections
__device__ float g_A[MROWS * EMBED];                          // attention context (tf32-rounded)
__device__ float g_X[MROWS * EMBED];                          // tf32-rounded query
__device__ float g_Wi[3 * EMBED * EMBED];                     // tf32-rounded in_proj_weight
__device__ float g_Wo[EMBED * EMBED];                         // tf32-rounded out_w

__device__ __forceinline__ uint32_t f2tf(float f) {
    uint32_t u;
    asm("cvt.rna.tf32.f32 %0, %1;" : "=r"(u) : "f"(f));
    return u;
}
__device__ __forceinline__ float f2tff(float f) { 
    uint32_t u = f2tf(f);
    return __uint_as_float(u);
}

__device__ __forceinline__ void mma_tf32(float* d, const uint32_t* a, const uint32_t* b) {
    asm volatile(
        "mma.sync.aligned.m16n8k8.row.col.f32.tf32.tf32.f32 "
        "{%0,%1,%2,%3}, {%4,%5,%6,%7}, {%8,%9}, {%0,%1,%2,%3};"
        : "+f"(d[0]), "+f"(d[1]), "+f"(d[2]), "+f"(d[3])
        : "r"(a[0]), "r"(a[1]), "r"(a[2]), "r"(a[3]), "r"(b[0]), "r"(b[1]));
}

__device__ __forceinline__ void cp16(uint32_t s, const void* g) {
    asm volatile("cp.async.cg.shared.global [%0], [%1], 16;" :: "r"(s), "l"(g));
}

// ---------------------------------------------------------------------------
// K0: round inputs to the tf32 grid (RNA) once, so the GEMM mainloops can
// cp.async raw bits and the HW's tf32 truncation is a no-op (bit-identical).
// ---------------------------------------------------------------------------
#define CVT_N_X  1048576   // 4096*1024/4
#define CVT_N_WI 786432    // 3072*1024/4
#define CVT_N_WO 262144    // 1024*1024/4
__global__ __launch_bounds__(256) void k_cvt(const float4* __restrict__ q,
                                             const float4* __restrict__ wi,
                                             const float4* __restrict__ wo) {
    int idx = blockIdx.x * 256 + threadIdx.x;
    const float4* src;
    float4* dst;
    int off;
    if (idx < CVT_N_X)                    { src = q;  dst = (float4*)g_X;  off = idx; }
    else if (idx < CVT_N_X + CVT_N_WI)    { src = wi; dst = (float4*)g_Wi; off = idx - CVT_N_X; }
    else                                  { src = wo; dst = (float4*)g_Wo; off = idx - CVT_N_X - CVT_N_WI; }
    float4 v = src[off];
    dst[off] = make_float4(f2tff(v.x), f2tff(v.y), f2tff(v.z), f2tff(v.w));
}

// ---------------------------------------------------------------------------
// TF32 tensor-core GEMM with cp.async mainloop (no STS/CVT in hot loop).
// CTA 128x128, BK=32, double-buffered smem, R8 conflict-free fragment layout.
// EPI=0: A=g_X, B=g_Wi, scatter into g_Q/g_K/g_V. EPI=1: A=g_A, B=g_Wo, C out.
// ---------------------------------------------------------------------------
#define GEMM_SMEM_WORDS (4 * 128 * 36)
#define AS(buf, r, c) As[(buf) * 4608 + (r) * 36 + (c)]
#define BS(buf, r, c) Bs[(buf) * 4608 + (r) * 36 + (c)]

template <int EPI>
__global__ __launch_bounds__(256) void k_gemm_tf32(const float* __restrict__ bias,
                                                   float* __restrict__ C,
                                                   int K) {
    const float* A = (EPI == 0) ? (const float*)g_X : (const float*)g_A;
    const float* B = (EPI == 0) ? (const float*)g_Wi : (const float*)g_Wo;
    extern __shared__ uint32_t smraw[];
    uint32_t* As = smraw;
    uint32_t* Bs = smraw + 2 * 4608;
    const uint32_t smA = (uint32_t)__cvta_generic_to_shared(smraw);
    const uint32_t smB = smA + 2 * 4608 * 4;
    const int tid  = threadIdx.x;
    const int lane = tid & 31;
    const int wid  = tid >> 5;
    const int wm   = (wid & 1) << 6;
    const int wn   = (wid >> 1) << 5;
    const int m0   = blockIdx.y << 7;
    const int n0   = blockIdx.x << 7;
    const int ldr = tid >> 3;
    const int ldc = (tid & 7) << 2;
    const int g4 = lane >> 2;
    const int g1 = lane & 3;

    float acc[4][4][4] = {};

    const float* Abase = A + (size_t)(m0 + ldr) * K + ldc;
    const float* Bbase = B + (size_t)(n0 + ldr) * K + ldc;
    const uint32_t stoff = (ldr * 36 + ldc) * 4;

    // prologue: stage 0
    #pragma unroll
    for (int r = 0; r < 4; r++) {
        cp16(smA + stoff + (r << 5) * 144, Abase + (size_t)(r << 5) * K);
        cp16(smB + stoff + (r << 5) * 144, Bbase + (size_t)(r << 5) * K);
    }
    asm volatile("cp.async.commit_group;");

    int cur = 0;
    for (int k0 = 0; k0 < K; k0 += 32) {
        const bool has_next = (k0 + 32 < K);
        if (has_next) {
            const uint32_t so = stoff + (cur ^ 1) * 18432;
            #pragma unroll
            for (int r = 0; r < 4; r++) {
                cp16(smA + so + (r << 5) * 144, Abase + (size_t)(r << 5) * K + k0 + 32);
                cp16(smB + so + (r << 5) * 144, Bbase + (size_t)(r << 5) * K + k0 + 32);
            }
            asm volatile("cp.async.commit_group;");
            asm volatile("cp.async.wait_group 1;");
        } else {
            asm volatile("cp.async.wait_group 0;");
        }
        __syncthreads();
        #pragma unroll
        for (int kk = 0; kk < 32; kk += 8) {
            uint32_t a[4][4], b[4][2];
            #pragma unroll
            for (int im = 0; im < 4; im++) {
                int mr = wm + (im << 4) + g4;
                a[im][0] = AS(cur, mr    , kk + g1    );
                a[im][1] = AS(cur, mr + 8, kk + g1    );
                a[im][2] = AS(cur, mr    , kk + g1 + 4);
                a[im][3] = AS(cur, mr + 8, kk + g1 + 4);
            }
            #pragma unroll
            for (int jn = 0; jn < 4; jn++) {
                int nr = wn + (jn << 3) + g4;
                b[jn][0] = BS(cur, nr, kk + g1    );
                b[jn][1] = BS(cur, nr, kk + g1 + 4);
            }
            #pragma unroll
            for (int im = 0; im < 4; im++)
                #pragma unroll
                for (int jn = 0; jn < 4; jn++)
                    mma_tf32(acc[im][jn], a[im], b[jn]);
        }
        __syncthreads();
        cur ^= 1;
    }

    #pragma unroll
    for (int im = 0; im < 4; im++)
        #pragma unroll
        for (int jn = 0; jn < 4; jn++)
            #pragma unroll
            for (int e = 0; e < 4; e++) {
                int m = m0 + wm + (im << 4) + g4 + ((e >> 1) << 3);
                int n = n0 + wn + (jn << 3) + (g1 << 1) + (e & 1);
                float v = acc[im][jn][e] + bias[n];
                if (EPI == 0) {
                    int t = m >> 2, bb = m & 3;
                    int c = n >> 10;
                    int ee = n & 1023;
                    int h = ee >> 6, d = ee & 63;
                    int idx = (((bb << 4) + h) * TLEN + t) * HD + d;
                    if (c == 0)      g_Q[idx] = v * QSCALE;
                    else if (c == 1) g_K[idx] = v;
                    else             g_V[idx] = v;
                } else {
                    C[(size_t)m * EMBED + n] = v;
                }
            }
}

// ---------------------------------------------------------------------------
// Fused flash attention — EXACT R8 version (1 CTA/SM), except the g_A store
// is tf32-RNA-rounded so oproj's cp.async path is bit-identical.
// ---------------------------------------------------------------------------
#define ATT_OFF_Q   0            // 128x68 words
#define ATT_OFF_K   8704         // 64x68
#define ATT_OFF_V   13056        // 64x68 (transposed: [d][s])
#define ATT_OFF_P   17408        // 128x68
#define ATT_OFF_RED 26112        // redm[4][128] + reds[4][128]
#define ATT_OFF_MT  27136        // m_tile[128][16]
#define ATT_OFF_PAD 29184        // 64 ints
#define ATT_SMEM_WORDS 29248

__global__ __launch_bounds__(256) void k_attn(const int* __restrict__ pad) {
    extern __shared__ uint32_t sm[];
    uint32_t* Qs = sm + ATT_OFF_Q;
    uint32_t* Ks = sm + ATT_OFF_K;
    uint32_t* Vs = sm + ATT_OFF_V;
    uint32_t* Ps = sm + ATT_OFF_P;
    float* redm = (float*)(sm + ATT_OFF_RED);
    float* reds = redm + 512;
    float* mtl  = (float*)(sm + ATT_OFF_MT);
    int*   pads = (int*)(sm + ATT_OFF_PAD);

    const int bh = blockIdx.y;
    const int t0 = (7 - blockIdx.x) << 7;
    const int b  = bh >> 4;
    const int h  = bh & 15;
    const int tid  = threadIdx.x;
    const int lane = tid & 31;
    const int wid  = tid >> 5;
    const int wm = (wid & 1) << 6;
    const int wn = (wid >> 1) << 4;
    const int g4 = lane >> 2;
    const int g1 = lane & 3;
    const int wc = wid >> 1;

    const float* Qg = g_Q + (size_t)bh * TLEN * HD;
    const float* Kg = g_K + (size_t)bh * TLEN * HD;
    const float* Vg = g_V + (size_t)bh * TLEN * HD;
    float* Pg = g_P + (size_t)bh * TLEN * TLEN;

    {
        int qr = tid >> 1;
        int qc = (tid & 1) << 5;
        #pragma unroll
        for (int j = 0; j < 8; j++) {
            float4 q = *(const float4*)(Qg + (size_t)(t0 + qr) * HD + qc + j * 4);
            uint32_t* p = &Qs[qr * 68 + qc + j * 4];
            p[0] = f2tf(q.x); p[1] = f2tf(q.y); p[2] = f2tf(q.z); p[3] = f2tf(q.w);
        }
    }

    float m_run[4][2], l_run[4][2];
    float acc_o[4][2][4] = {};
    #pragma unroll
    for (int im = 0; im < 4; im++) {
        m_run[im][0] = m_run[im][1] = -1e30f;
        l_run[im][0] = l_run[im][1] = 0.f;
    }
    __syncthreads();

    const int nt = (t0 + 128) >> 6;
    const int kr = tid >> 2;
    const int kc = (tid & 3) << 4;

    for (int it = 0; it < nt; it++) {
        const int s0 = it << 6;
        float4 kf[4], vf[4];
        #pragma unroll
        for (int j = 0; j < 4; j++) {
            kf[j] = *(const float4*)(Kg + (size_t)(s0 + kr) * HD + kc + j * 4);
            vf[j] = *(const float4*)(Vg + (size_t)(s0 + kr) * HD + kc + j * 4);
        }
        int padv = (tid < 64) ? pad[b * TLEN + s0 + tid] : 0;
        __syncthreads();
        #pragma unroll
        for (int j = 0; j < 4; j++) {
            uint32_t* p = &Ks[kr * 68 + kc + j * 4];
            p[0] = f2tf(kf[j].x); p[1] = f2tf(kf[j].y); p[2] = f2tf(kf[j].z); p[3] = f2tf(kf[j].w);
            Vs[(kc + j * 4 + 0) * 68 + kr] = f2tf(vf[j].x);
            Vs[(kc + j * 4 + 1) * 68 + kr] = f2tf(vf[j].y);
            Vs[(kc + j * 4 + 2) * 68 + kr] = f2tf(vf[j].z);
            Vs[(kc + j * 4 + 3) * 68 + kr] = f2tf(vf[j].w);
        }
        if (tid < 64) pads[tid] = padv;
        __syncthreads();

        float accs[4][2][4] = {};
        #pragma unroll
        for (int kk = 0; kk < 64; kk += 8) {
            uint32_t a[4][4], bf[2][2];
            #pragma unroll
            for (int im = 0; im < 4; im++) {
                int mr = wm + (im << 4) + g4;
                a[im][0] = Qs[mr * 68 + kk + g1];
                a[im][1] = Qs[(mr + 8) * 68 + kk + g1];
                a[im][2] = Qs[mr * 68 + kk + g1 + 4];
                a[im][3] = Qs[(mr + 8) * 68 + kk + g1 + 4];
            }
            #pragma unroll
            for (int jn = 0; jn < 2; jn++) {
                int nr = wn + (jn << 3) + g4;
                bf[jn][0] = Ks[nr * 68 + kk + g1];
                bf[jn][1] = Ks[nr * 68 + kk + g1 + 4];
            }
            #pragma unroll
            for (int im = 0; im < 4; im++)
                #pragma unroll
                for (int jn = 0; jn < 2; jn++)
                    mma_tf32(accs[im][jn], a[im], bf[jn]);
        }

        float mloc[4][2];
        #pragma unroll
        for (int im = 0; im < 4; im++)
            #pragma unroll
            for (int ep = 0; ep < 2; ep++) {
                int t = t0 + wm + (im << 4) + g4 + (ep << 3);
                float mm = -1e30f;
                #pragma unroll
                for (int jn = 0; jn < 2; jn++)
                    #pragma unroll
                    for (int c = 0; c < 2; c++) {
                        int s = s0 + wn + (jn << 3) + (g1 << 1) + c;
                        bool ok = (s <= t) && (pads[s - s0] == 0);
                        float v = ok ? accs[im][jn][(ep << 1) + c] : -1e30f;
                        accs[im][jn][(ep << 1) + c] = v;
                        mm = fmaxf(mm, v);
                    }
                mm = fmaxf(mm, __shfl_xor_sync(0xffffffffu, mm, 1));
                mm = fmaxf(mm, __shfl_xor_sync(0xffffffffu, mm, 2));
                mloc[im][ep] = mm;
            }
        if (g1 == 0) {
            #pragma unroll
            for (int im = 0; im < 4; im++)
                #pragma unroll
                for (int ep = 0; ep < 2; ep++)
                    redm[wc * 128 + wm + (im << 4) + g4 + (ep << 3)] = mloc[im][ep];
        }
        __syncthreads();

        float m_new[4][2];
        #pragma unroll
        for (int im = 0; im < 4; im++)
            #pragma unroll
            for (int ep = 0; ep < 2; ep++) {
                int row = wm + (im << 4) + g4 + (ep << 3);
                float mt = fmaxf(fmaxf(redm[row], redm[128 + row]),
                                 fmaxf(redm[256 + row], redm[384 + row]));
                float mn = fmaxf(m_run[im][ep], mt);
                float f = __expf(m_run[im][ep] - mn);
                m_new[im][ep] = mn;
                m_run[im][ep] = mn;
                l_run[im][ep] *= f;
                #pragma unroll
                for (int jn = 0; jn < 2; jn++) {
                    acc_o[im][jn][(ep << 1) + 0] *= f;
                    acc_o[im][jn][(ep << 1) + 1] *= f;
                }
                if (wc == 0 && g1 == 0) mtl[row * 16 + it] = mn;
            }

        #pragma unroll
        for (int im = 0; im < 4; im++)
            #pragma unroll
            for (int ep = 0; ep < 2; ep++) {
                int t = t0 + wm + (im << 4) + g4 + (ep << 3);
                int rowL = t - t0;
                float ssum = 0.f;
                #pragma unroll
                for (int jn = 0; jn < 2; jn++) {
                    int cb = wn + (jn << 3) + (g1 << 1);
                    float p0 = __expf(accs[im][jn][(ep << 1) + 0] - m_new[im][ep]);
                    float p1 = __expf(accs[im][jn][(ep << 1) + 1] - m_new[im][ep]);
                    ssum += p0 + p1;
                    *(float2*)(Pg + (size_t)t * TLEN + s0 + cb) = make_float2(p0, p1);
                    Ps[rowL * 68 + cb]     = f2tf(p0);
                    Ps[rowL * 68 + cb + 1] = f2tf(p1);
                }
                ssum += __shfl_xor_sync(0xffffffffu, ssum, 1);
                ssum += __shfl_xor_sync(0xffffffffu, ssum, 2);
                if (g1 == 0) reds[wc * 128 + rowL] = ssum;
            }
        __syncthreads();
        #pragma unroll
        for (int im = 0; im < 4; im++)
            #pragma unroll
            for (int ep = 0; ep < 2; ep++) {
                int row = wm + (im << 4) + g4 + (ep << 3);
                l_run[im][ep] += reds[row] + reds[128 + row] + reds[256 + row] + reds[384 + row];
            }

        #pragma unroll
        for (int kk = 0; kk < 64; kk += 8) {
            uint32_t a[4][4], bf[2][2];
            #pragma unroll
            for (int im = 0; im < 4; im++) {
                int mr = wm + (im << 4) + g4;
                a[im][0] = Ps[mr * 68 + kk + g1];
                a[im][1] = Ps[(mr + 8) * 68 + kk + g1];
                a[im][2] = Ps[mr * 68 + kk + g1 + 4];
                a[im][3] = Ps[(mr + 8) * 68 + kk + g1 + 4];
            }
            #pragma unroll
            for (int jn = 0; jn < 2; jn++) {
                int nr = wn + (jn << 3) + g4;
                bf[jn][0] = Vs[nr * 68 + kk + g1];
                bf[jn][1] = Vs[nr * 68 + kk + g1 + 4];
            }
            #pragma unroll
            for (int im = 0; im < 4; im++)
                #pragma unroll
                for (int jn = 0; jn < 2; jn++)
                    mma_tf32(acc_o[im][jn], a[im], bf[jn]);
        }
    }

    // epilogue: O/l -> g_A (tf32-RNA-rounded for the cp.async oproj)
    #pragma unroll
    for (int im = 0; im < 4; im++)
        #pragma unroll
        for (int ep = 0; ep < 2; ep++) {
            int t = t0 + wm + (im << 4) + g4 + (ep << 3);
            float inv = 1.f / l_run[im][ep];
            #pragma unroll
            for (int jn = 0; jn < 2; jn++) {
                int d = wn + (jn << 3) + (g1 << 1);
                float* o = g_A + ((size_t)t * BATCH + b) * EMBED + (h << 6) + d;
                *(float2*)o = make_float2(f2tff(acc_o[im][jn][(ep << 1) + 0] * inv),
                                          f2tff(acc_o[im][jn][(ep << 1) + 1] * inv));
            }
        }
    if (wc == 0 && g1 == 0) {
        #pragma unroll
        for (int im = 0; im < 4; im++)
            #pragma unroll
            for (int ep = 0; ep < 2; ep++) {
                int row = wm + (im << 4) + g4 + (ep << 3);
                int t = t0 + row;
                float inv = 1.f / l_run[im][ep];
                float mfin = m_run[im][ep];
                for (int it2 = 0; it2 < nt; it2++) {
                    float c = __expf(mtl[row * 16 + it2] - mfin) * inv;
                    g_C[((size_t)bh * TLEN + t) * 16 + it2] = c;
                }
            }
    }
}

// ---------------------------------------------------------------------------
// avg_weights[b,t,s] = (1/16) sum_h P~[bh,t,s] * C[bh,t,s>>6]; 0 for s>t.
// ---------------------------------------------------------------------------
__global__ __launch_bounds__(256) void k_avg(float* __restrict__ outAvg) {
    const int idx = blockIdx.x * 256 + threadIdx.x;
    const int s = idx & 1023;
    const int t = (idx >> 10) & 1023;
    const int b = idx >> 20;
    if (s > t) { outAvg[idx] = 0.f; return; }
    const int tile = s >> 6;
    float sum = 0.f;
    #pragma unroll
    for (int h = 0; h < 16; h++) {
        size_t base = (size_t)((b << 4) + h) * TLEN + t;
        sum += g_P[base * TLEN + s] * g_C[base * 16 + tile];
    }
    outAvg[idx] = sum * 0.0625f;
}

// ---------------------------------------------------------------------------
extern "C" void kernel_launch(void* const* d_in, const int* in_sizes, int n_in,
                              void* d_out, int out_size) {
    const float* query = (const float*)d_in[0];
    const int*   mask  = (const int*)d_in[1];   // numpy bool widened to int32
    const float* w_in  = (const float*)d_in[2];
    const float* b_in  = (const float*)d_in[3];
    const float* w_out = (const float*)d_in[4];
    const float* b_out = (const float*)d_in[5];

    float* outAttn = (float*)d_out;                                   // [T,B,E]
    float* outAvg  = (float*)d_out + (size_t)MROWS * EMBED;           // [B,T,S]

    static cudaStream_t s_avg = nullptr;
    static cudaEvent_t ev_fork = nullptr, ev_join = nullptr;
    if (s_avg == nullptr) {
        cudaStreamCreateWithFlags(&s_avg, cudaStreamNonBlocking);
        cudaEventCreateWithFlags(&ev_fork, cudaEventDisableTiming);
        cudaEventCreateWithFlags(&ev_join, cudaEventDisableTiming);
    }

    const int gemm_smem = GEMM_SMEM_WORDS * 4;   // 73,728 B -> 2 CTAs/SM
    const int attn_smem = ATT_SMEM_WORDS * 4;    // 116,992 B (R8 config)
    cudaFuncSetAttribute(k_gemm_tf32<0>, cudaFuncAttributeMaxDynamicSharedMemorySize, gemm_smem);
    cudaFuncSetAttribute(k_gemm_tf32<1>, cudaFuncAttributeMaxDynamicSharedMemorySize, gemm_smem);
    cudaFuncSetAttribute(k_attn,         cudaFuncAttributeMaxDynamicSharedMemorySize, attn_smem);

    k_cvt<<<8192, 256>>>((const float4*)query, (const float4*)w_in, (const float4*)w_out);
    k_gemm_tf32<0><<<dim3(24, 32), 256, gemm_smem>>>(b_in, nullptr, EMBED);
    k_attn<<<dim3(8, 64), 256, attn_smem>>>(mask);

    cudaEventRecord(ev_fork, 0);
    cudaStreamWaitEvent(s_avg, ev_fork, 0);
    k_avg<<<16384, 256, 0, s_avg>>>(outAvg);
    cudaEventRecord(ev_join, s_avg);

    k_gemm_tf32<1><<<dim3(8, 32), 256, gemm_smem>>>(b_out, outAttn, EMBED);

    cudaStreamWaitEvent(0, ev_join, 0);
}

// round 13
// speedup vs baseline: 1.3976x; 1.1098x over previous
#include <cuda_runtime.h>
#include <math.h>
#include <stdint.h>

#define TLEN   1024
#define BATCH  4
#define EMBED  1024
#define NH     16
#define HD     64
#define QSCALE 0.125f
#define MROWS  (TLEN * BATCH)   // 4096

// Scratch (static device globals — no cudaMalloc anywhere)
__device__ float g_Q[BATCH * NH * TLEN * HD];                 // [b,h,t,d], pre-scaled
__device__ float g_K[BATCH * NH * TLEN * HD];
__device__ float g_V[BATCH * NH * TLEN * HD];
__device__ float g_P[(size_t)BATCH * NH * TLEN * TLEN];       // unnormalized exp tiles
__device__ float g_C[BATCH * NH * TLEN * 16];                 // per-(row,tile) corrections
__device__ float g_A[MROWS * EMBED];                          // attention context [t,b,e]

__device__ __forceinline__ uint32_t f2tf(float f) {
    uint32_t u;
    asm("cvt.rna.tf32.f32 %0, %1;" : "=r"(u) : "f"(f));
    return u;
}

__device__ __forceinline__ void mma_tf32(float* d, const uint32_t* a, const uint32_t* b) {
    asm volatile(
        "mma.sync.aligned.m16n8k8.row.col.f32.tf32.tf32.f32 "
        "{%0,%1,%2,%3}, {%4,%5,%6,%7}, {%8,%9}, {%0,%1,%2,%3};"
        : "+f"(d[0]), "+f"(d[1]), "+f"(d[2]), "+f"(d[3])
        : "r"(a[0]), "r"(a[1]), "r"(a[2]), "r"(a[3]), "r"(b[0]), "r"(b[1]));
}

// ---------------------------------------------------------------------------
// TF32 tensor-core GEMM (EXACT R8 version — proven 498us config)
// CTA 128x128, BK=32, 8 warps (2m x 4n), double-buffered dynamic smem.
// EPI=0: A=query arg, scatter into g_Q/g_K/g_V. EPI=1: A=g_A (device), C out.
// ---------------------------------------------------------------------------
#define GEMM_SMEM_WORDS (4 * 128 * 36)
#define AS(buf, r, c) As[(buf) * 4608 + (r) * 36 + (c)]
#define BS(buf, r, c) Bs[(buf) * 4608 + (r) * 36 + (c)]

template <int EPI>
__global__ __launch_bounds__(256) void k_gemm_tf32(const float* __restrict__ Ain,
                                                   const float* __restrict__ B,
                                                   const float* __restrict__ bias,
                                                   float* __restrict__ C,
                                                   int K) {
    const float* A = (EPI == 0) ? Ain : (const float*)g_A;
    extern __shared__ uint32_t smraw[];
    uint32_t* As = smraw;
    uint32_t* Bs = smraw + 2 * 4608;
    const int tid  = threadIdx.x;
    const int lane = tid & 31;
    const int wid  = tid >> 5;
    const int wm   = (wid & 1) << 6;
    const int wn   = (wid >> 1) << 5;
    const int m0   = blockIdx.y << 7;
    const int n0   = blockIdx.x << 7;
    const int ldr = tid >> 3;
    const int ldc = (tid & 7) << 2;
    const int g4 = lane >> 2;
    const int g1 = lane & 3;

    float acc[4][4][4] = {};
    float4 av[4], bv[4];

    const float* Abase = A + (size_t)(m0 + ldr) * K + ldc;
    const float* Bbase = B + (size_t)(n0 + ldr) * K + ldc;

    #pragma unroll
    for (int r = 0; r < 4; r++) {
        av[r] = *(const float4*)(Abase + (size_t)(r << 5) * K);
        bv[r] = *(const float4*)(Bbase + (size_t)(r << 5) * K);
    }
    #pragma unroll
    for (int r = 0; r < 4; r++) {
        uint32_t* pa = &AS(0, (r << 5) + ldr, ldc);
        uint32_t* pb = &BS(0, (r << 5) + ldr, ldc);
        pa[0] = f2tf(av[r].x); pa[1] = f2tf(av[r].y); pa[2] = f2tf(av[r].z); pa[3] = f2tf(av[r].w);
        pb[0] = f2tf(bv[r].x); pb[1] = f2tf(bv[r].y); pb[2] = f2tf(bv[r].z); pb[3] = f2tf(bv[r].w);
    }
    __syncthreads();

    int cur = 0;
    for (int k0 = 0; k0 < K; k0 += 32) {
        const bool has_next = (k0 + 32 < K);
        if (has_next) {
            #pragma unroll
            for (int r = 0; r < 4; r++) {
                av[r] = *(const float4*)(Abase + (size_t)(r << 5) * K + k0 + 32);
                bv[r] = *(const float4*)(Bbase + (size_t)(r << 5) * K + k0 + 32);
            }
        }
        #pragma unroll
        for (int kk = 0; kk < 32; kk += 8) {
            uint32_t a[4][4], b[4][2];
            #pragma unroll
            for (int im = 0; im < 4; im++) {
                int mr = wm + (im << 4) + g4;
                a[im][0] = AS(cur, mr    , kk + g1    );
                a[im][1] = AS(cur, mr + 8, kk + g1    );
                a[im][2] = AS(cur, mr    , kk + g1 + 4);
                a[im][3] = AS(cur, mr + 8, kk + g1 + 4);
            }
            #pragma unroll
            for (int jn = 0; jn < 4; jn++) {
                int nr = wn + (jn << 3) + g4;
                b[jn][0] = BS(cur, nr, kk + g1    );
                b[jn][1] = BS(cur, nr, kk + g1 + 4);
            }
            #pragma unroll
            for (int im = 0; im < 4; im++)
                #pragma unroll
                for (int jn = 0; jn < 4; jn++)
                    mma_tf32(acc[im][jn], a[im], b[jn]);
        }
        if (has_next) {
            int nxt = cur ^ 1;
            #pragma unroll
            for (int r = 0; r < 4; r++) {
                uint32_t* pa = &AS(nxt, (r << 5) + ldr, ldc);
                uint32_t* pb = &BS(nxt, (r << 5) + ldr, ldc);
                pa[0] = f2tf(av[r].x); pa[1] = f2tf(av[r].y); pa[2] = f2tf(av[r].z); pa[3] = f2tf(av[r].w);
                pb[0] = f2tf(bv[r].x); pb[1] = f2tf(bv[r].y); pb[2] = f2tf(bv[r].z); pb[3] = f2tf(bv[r].w);
            }
            __syncthreads();
        }
        cur ^= 1;
    }

    #pragma unroll
    for (int im = 0; im < 4; im++)
        #pragma unroll
        for (int jn = 0; jn < 4; jn++)
            #pragma unroll
            for (int e = 0; e < 4; e++) {
                int m = m0 + wm + (im << 4) + g4 + ((e >> 1) << 3);
                int n = n0 + wn + (jn << 3) + (g1 << 1) + (e & 1);
                float v = acc[im][jn][e] + bias[n];
                if (EPI == 0) {
                    int t = m >> 2, bb = m & 3;
                    int c = n >> 10;
                    int ee = n & 1023;
                    int h = ee >> 6, d = ee & 63;
                    int idx = (((bb << 4) + h) * TLEN + t) * HD + d;
                    if (c == 0)      g_Q[idx] = v * QSCALE;
                    else if (c == 1) g_K[idx] = v;
                    else             g_V[idx] = v;
                } else {
                    C[(size_t)m * EMBED + n] = v;
                }
            }
}

// ---------------------------------------------------------------------------
// Fused flash attention, warp-per-16-rows layout:
//  - each warp owns 16 t-rows x all 64 s-cols -> softmax is warp-local
//    (2 shfl.xor), no cross-warp smem reductions, 2 syncs/iter instead of 4
//  - P stays in registers: V is stored with per-8-group column permutation
//    tau(v) = (v>>1) | ((v&1)<<2) so S C-layout regs ARE valid A-fragments.
// smem: Q 128x68, K 64x68, V 64x68(perm), mtl 128x16, pad 64  = 78,080 B
// ---------------------------------------------------------------------------
#define ATT_OFF_Q   0
#define ATT_OFF_K   8704
#define ATT_OFF_V   13056
#define ATT_OFF_MT  17408
#define ATT_OFF_PAD 19456
#define ATT_SMEM_WORDS 19520

__global__ __launch_bounds__(256) void k_attn(const int* __restrict__ pad) {
    extern __shared__ uint32_t sm[];
    uint32_t* Qs = sm + ATT_OFF_Q;
    uint32_t* Ks = sm + ATT_OFF_K;
    uint32_t* Vs = sm + ATT_OFF_V;
    float* mtl  = (float*)(sm + ATT_OFF_MT);
    int*   pads = (int*)(sm + ATT_OFF_PAD);

    const int bh = blockIdx.y;
    const int t0 = (7 - blockIdx.x) << 7;      // big tiles first
    const int b  = bh >> 4;
    const int h  = bh & 15;
    const int tid  = threadIdx.x;
    const int lane = tid & 31;
    const int wid  = tid >> 5;
    const int wm = wid << 4;                   // warp's 16-row block
    const int g4 = lane >> 2;
    const int g1 = lane & 3;

    const float* Qg = g_Q + (size_t)bh * TLEN * HD;
    const float* Kg = g_K + (size_t)bh * TLEN * HD;
    const float* Vg = g_V + (size_t)bh * TLEN * HD;
    float* Pg = g_P + (size_t)bh * TLEN * TLEN;

    // Q tile 128x64 -> smem (tf32)
    {
        int qr = tid >> 1;
        int qc = (tid & 1) << 5;
        #pragma unroll
        for (int j = 0; j < 8; j++) {
            float4 q = *(const float4*)(Qg + (size_t)(t0 + qr) * HD + qc + j * 4);
            uint32_t* p = &Qs[qr * 68 + qc + j * 4];
            p[0] = f2tf(q.x); p[1] = f2tf(q.y); p[2] = f2tf(q.z); p[3] = f2tf(q.w);
        }
    }

    // rows owned by this thread: r0 = t0+wm+g4, r1 = r0+8
    const int row0 = wm + g4;
    const int row1 = wm + g4 + 8;
    float m_run0 = -1e30f, m_run1 = -1e30f;
    float l_run0 = 0.f, l_run1 = 0.f;
    float acc_o[8][4] = {};
    __syncthreads();

    const int nt = (t0 + 128) >> 6;
    const int kr = tid >> 2;                               // s row 0..63
    const int kc = (tid & 3) << 4;                         // d col base
    const int krp = (kr & 56) | ((kr & 7) >> 1) | ((kr & 1) << 2);  // permuted s col

    for (int it = 0; it < nt; it++) {
        const int s0 = it << 6;
        float4 kf[4], vf[4];
        #pragma unroll
        for (int j = 0; j < 4; j++) {
            kf[j] = *(const float4*)(Kg + (size_t)(s0 + kr) * HD + kc + j * 4);
            vf[j] = *(const float4*)(Vg + (size_t)(s0 + kr) * HD + kc + j * 4);
        }
        int padv = (tid < 64) ? pad[b * TLEN + s0 + tid] : 0;
        __syncthreads();                       // prev tile's Ks/Vs consumed
        #pragma unroll
        for (int j = 0; j < 4; j++) {
            uint32_t* p = &Ks[kr * 68 + kc + j * 4];
            p[0] = f2tf(kf[j].x); p[1] = f2tf(kf[j].y); p[2] = f2tf(kf[j].z); p[3] = f2tf(kf[j].w);
            Vs[(kc + j * 4 + 0) * 68 + krp] = f2tf(vf[j].x);
            Vs[(kc + j * 4 + 1) * 68 + krp] = f2tf(vf[j].y);
            Vs[(kc + j * 4 + 2) * 68 + krp] = f2tf(vf[j].z);
            Vs[(kc + j * 4 + 3) * 68 + krp] = f2tf(vf[j].w);
        }
        if (tid < 64) pads[tid] = padv;
        __syncthreads();

        // ---- S = Q K^T : 16 rows x 64 cols per warp ----
        float accs[8][4] = {};
        #pragma unroll
        for (int kk = 0; kk < 64; kk += 8) {
            uint32_t a[4];
            a[0] = Qs[row0 * 68 + kk + g1];
            a[1] = Qs[row1 * 68 + kk + g1];
            a[2] = Qs[row0 * 68 + kk + g1 + 4];
            a[3] = Qs[row1 * 68 + kk + g1 + 4];
            #pragma unroll
            for (int jn = 0; jn < 8; jn++) {
                uint32_t bf[2];
                int nr = (jn << 3) + g4;
                bf[0] = Ks[nr * 68 + kk + g1];
                bf[1] = Ks[nr * 68 + kk + g1 + 4];
                mma_tf32(accs[jn], a, bf);
            }
        }

        // ---- mask + warp-local row max ----
        const int tg0 = t0 + row0;
        const int tg1 = t0 + row1;
        float m0 = -1e30f, m1 = -1e30f;
        #pragma unroll
        for (int jn = 0; jn < 8; jn++) {
            #pragma unroll
            for (int c = 0; c < 2; c++) {
                int s = s0 + (jn << 3) + (g1 << 1) + c;
                int pv = pads[s - s0];
                bool ok0 = (s <= tg0) && (pv == 0);
                bool ok1 = (s <= tg1) && (pv == 0);
                float v0 = ok0 ? accs[jn][c]     : -1e30f;
                float v1 = ok1 ? accs[jn][2 + c] : -1e30f;
                accs[jn][c]     = v0;
                accs[jn][2 + c] = v1;
                m0 = fmaxf(m0, v0);
                m1 = fmaxf(m1, v1);
            }
        }
        m0 = fmaxf(m0, __shfl_xor_sync(0xffffffffu, m0, 1));
        m0 = fmaxf(m0, __shfl_xor_sync(0xffffffffu, m0, 2));
        m1 = fmaxf(m1, __shfl_xor_sync(0xffffffffu, m1, 1));
        m1 = fmaxf(m1, __shfl_xor_sync(0xffffffffu, m1, 2));

        // ---- online update ----
        float mn0 = fmaxf(m_run0, m0);
        float mn1 = fmaxf(m_run1, m1);
        float f0 = __expf(m_run0 - mn0);
        float f1 = __expf(m_run1 - mn1);
        m_run0 = mn0; m_run1 = mn1;
        l_run0 *= f0;  l_run1 *= f1;
        #pragma unroll
        for (int dn = 0; dn < 8; dn++) {
            acc_o[dn][0] *= f0; acc_o[dn][1] *= f0;
            acc_o[dn][2] *= f1; acc_o[dn][3] *= f1;
        }
        if (g1 == 0) {
            mtl[row0 * 16 + it] = mn0;
            mtl[row1 * 16 + it] = mn1;
        }

        // ---- exp, gmem P write, row sums, build A-fragments ----
        uint32_t pa[8][4];
        float sum0 = 0.f, sum1 = 0.f;
        #pragma unroll
        for (int jn = 0; jn < 8; jn++) {
            int cb = s0 + (jn << 3) + (g1 << 1);
            float p00 = __expf(accs[jn][0] - mn0);
            float p01 = __expf(accs[jn][1] - mn0);
            float p10 = __expf(accs[jn][2] - mn1);
            float p11 = __expf(accs[jn][3] - mn1);
            sum0 += p00 + p01;
            sum1 += p10 + p11;
            *(float2*)(Pg + (size_t)tg0 * TLEN + cb) = make_float2(p00, p01);
            *(float2*)(Pg + (size_t)tg1 * TLEN + cb) = make_float2(p10, p11);
            pa[jn][0] = f2tf(p00);   // (row g4,   A-col g1)   = S col 2g1
            pa[jn][1] = f2tf(p10);   // (row g4+8, A-col g1)
            pa[jn][2] = f2tf(p01);   // (row g4,   A-col g1+4) = S col 2g1+1
            pa[jn][3] = f2tf(p11);
        }
        sum0 += __shfl_xor_sync(0xffffffffu, sum0, 1);
        sum0 += __shfl_xor_sync(0xffffffffu, sum0, 2);
        sum1 += __shfl_xor_sync(0xffffffffu, sum1, 1);
        sum1 += __shfl_xor_sync(0xffffffffu, sum1, 2);
        l_run0 += sum0;
        l_run1 += sum1;

        // ---- O += P~ V : P from registers, V permuted in smem ----
        #pragma unroll
        for (int ks = 0; ks < 8; ks++) {
            #pragma unroll
            for (int dn = 0; dn < 8; dn++) {
                uint32_t bf[2];
                int nr = (dn << 3) + g4;
                bf[0] = Vs[nr * 68 + (ks << 3) + g1];
                bf[1] = Vs[nr * 68 + (ks << 3) + g1 + 4];
                mma_tf32(acc_o[dn], pa[ks], bf);
            }
        }
    }

    // ---- epilogue: O/l -> g_A; corrections -> g_C ----
    const int tg0 = t0 + row0;
    const int tg1 = t0 + row1;
    float inv0 = 1.f / l_run0;
    float inv1 = 1.f / l_run1;
    #pragma unroll
    for (int dn = 0; dn < 8; dn++) {
        int d = (dn << 3) + (g1 << 1);
        float* o0 = g_A + ((size_t)tg0 * BATCH + b) * EMBED + (h << 6) + d;
        float* o1 = g_A + ((size_t)tg1 * BATCH + b) * EMBED + (h << 6) + d;
        *(float2*)o0 = make_float2(acc_o[dn][0] * inv0, acc_o[dn][1] * inv0);
        *(float2*)o1 = make_float2(acc_o[dn][2] * inv1, acc_o[dn][3] * inv1);
    }
    if (g1 == 0) {
        for (int it2 = 0; it2 < nt; it2++) {
            g_C[((size_t)bh * TLEN + tg0) * 16 + it2] = __expf(mtl[row0 * 16 + it2] - m_run0) * inv0;
            g_C[((size_t)bh * TLEN + tg1) * 16 + it2] = __expf(mtl[row1 * 16 + it2] - m_run1) * inv1;
        }
    }
}

// ---------------------------------------------------------------------------
// avg_weights[b,t,s] = (1/16) sum_h P~[bh,t,s] * C[bh,t,s>>6]; 0 for s>t.
// ---------------------------------------------------------------------------
__global__ __launch_bounds__(256) void k_avg(float* __restrict__ outAvg) {
    const int idx = blockIdx.x * 256 + threadIdx.x;
    const int s = idx & 1023;
    const int t = (idx >> 10) & 1023;
    const int b = idx >> 20;
    if (s > t) { outAvg[idx] = 0.f; return; }
    const int tile = s >> 6;
    float sum = 0.f;
    #pragma unroll
    for (int h = 0; h < 16; h++) {
        size_t base = (size_t)((b << 4) + h) * TLEN + t;
        sum += g_P[base * TLEN + s] * g_C[base * 16 + tile];
    }
    outAvg[idx] = sum * 0.0625f;
}

// ---------------------------------------------------------------------------
extern "C" void kernel_launch(void* const* d_in, const int* in_sizes, int n_in,
                              void* d_out, int out_size) {
    const float* query = (const float*)d_in[0];
    const int*   mask  = (const int*)d_in[1];   // numpy bool widened to int32
    const float* w_in  = (const float*)d_in[2];
    const float* b_in  = (const float*)d_in[3];
    const float* w_out = (const float*)d_in[4];
    const float* b_out = (const float*)d_in[5];

    float* outAttn = (float*)d_out;                                   // [T,B,E]
    float* outAvg  = (float*)d_out + (size_t)MROWS * EMBED;           // [B,T,S]

    static cudaStream_t s_avg = nullptr;
    static cudaEvent_t ev_fork = nullptr, ev_join = nullptr;
    if (s_avg == nullptr) {
        cudaStreamCreateWithFlags(&s_avg, cudaStreamNonBlocking);
        cudaEventCreateWithFlags(&ev_fork, cudaEventDisableTiming);
        cudaEventCreateWithFlags(&ev_join, cudaEventDisableTiming);
    }

    const int gemm_smem = GEMM_SMEM_WORDS * 4;   // 73,728 B
    const int attn_smem = ATT_SMEM_WORDS * 4;    // 78,080 B
    cudaFuncSetAttribute(k_gemm_tf32<0>, cudaFuncAttributeMaxDynamicSharedMemorySize, gemm_smem);
    cudaFuncSetAttribute(k_gemm_tf32<1>, cudaFuncAttributeMaxDynamicSharedMemorySize, gemm_smem);
    cudaFuncSetAttribute(k_attn,         cudaFuncAttributeMaxDynamicSharedMemorySize, attn_smem);

    k_gemm_tf32<0><<<dim3(24, 32), 256, gemm_smem>>>(query, w_in, b_in, nullptr, EMBED);
    k_attn<<<dim3(8, 64), 256, attn_smem>>>(mask);

    // Fork: avg depends only on k_attn; run concurrently with out-proj.
    cudaEventRecord(ev_fork, 0);
    cudaStreamWaitEvent(s_avg, ev_fork, 0);
    k_avg<<<16384, 256, 0, s_avg>>>(outAvg);
    cudaEventRecord(ev_join, s_avg);

    k_gemm_tf32<1><<<dim3(8, 32), 256, gemm_smem>>>(nullptr, w_out, b_out, outAttn, EMBED);

    cudaStreamWaitEvent(0, ev_join, 0);
}